// round 1
// baseline (speedup 1.0000x reference)
#include <cuda_runtime.h>

// Segment mean pooling:
//   x: [N=524288, D=128] float32
//   pointer: [B+1=1025] int32 (CSR offsets)
//   out: [B=1024, D=128] float32, out[b] = mean(x[pointer[b]:pointer[b+1]]), empty -> 0
//
// One CTA per segment. 256 threads: 32 float4-columns x 8 row-lanes.
// Fully coalesced: each row is 512B contiguous; a row-lane's 32 threads issue
// one 512B transaction per row.

#define D_FEAT 128
#define D4 (D_FEAT / 4)   // 32 float4 per row

__global__ __launch_bounds__(256) void seg_mean_kernel(
    const float4* __restrict__ x4,
    const int* __restrict__ ptr,
    float4* __restrict__ out4)
{
    const int seg = blockIdx.x;
    const int start = ptr[seg];
    const int end   = ptr[seg + 1];

    const int c4 = threadIdx.x & 31;   // float4 column 0..31
    const int r  = threadIdx.x >> 5;   // row lane 0..7

    float4 acc = make_float4(0.f, 0.f, 0.f, 0.f);

    // Each row-lane strides by 8 rows; loads are independent -> front-batched MLP.
    int row = start + r;
    #pragma unroll 4
    for (; row < end; row += 8) {
        const float4 v = x4[(size_t)row * D4 + c4];
        acc.x += v.x; acc.y += v.y; acc.z += v.z; acc.w += v.w;
    }

    // Reduce the 8 row-lanes' partials per column.
    __shared__ float4 sacc[8][D4];
    sacc[r][c4] = acc;
    __syncthreads();

    if (r == 0) {
        #pragma unroll
        for (int i = 1; i < 8; i++) {
            const float4 v = sacc[i][c4];
            acc.x += v.x; acc.y += v.y; acc.z += v.z; acc.w += v.w;
        }
        const int cnt = end - start;
        const float inv = 1.0f / (float)(cnt > 0 ? cnt : 1);
        acc.x *= inv; acc.y *= inv; acc.z *= inv; acc.w *= inv;
        out4[(size_t)seg * D4 + c4] = acc;
    }
}

extern "C" void kernel_launch(void* const* d_in, const int* in_sizes, int n_in,
                              void* d_out, int out_size)
{
    const float4* x4  = (const float4*)d_in[0];
    const int*    ptr = (const int*)d_in[1];
    float4*       o4  = (float4*)d_out;

    const int n_graphs = in_sizes[1] - 1;   // 1024
    seg_mean_kernel<<<n_graphs, 256>>>(x4, ptr, o4);
}

// round 2
// speedup vs baseline: 1.2243x; 1.2243x over previous
#include <cuda_runtime.h>

// Segment mean pooling, split-K formulation:
//   x: [N=524288, D=128] f32, pointer: [B+1=1025] i32, out: [B=1024, D=128] f32.
//
// Kernel 1: zero out.
// Kernel 2: uniform 256-row chunks per CTA (perfect load balance); each thread
//           accumulates a float4 over its stride-8 rows, flushing to global
//           atomics whenever its row crosses a segment boundary (pointer table
//           staged in smem, cursor walk handles empty segments for free).
// Kernel 3: scale each segment row by 1/max(count,1).

#define D_FEAT 128
#define D4 (D_FEAT / 4)       // 32 float4 per row
#define CHUNK 256             // rows per CTA
#define MAX_PTR 1040          // >= B+1 = 1025

__global__ __launch_bounds__(256) void zero_out_kernel(float4* __restrict__ out4, int n4)
{
    int i = blockIdx.x * blockDim.x + threadIdx.x;
    if (i < n4) out4[i] = make_float4(0.f, 0.f, 0.f, 0.f);
}

__global__ __launch_bounds__(256) void seg_accum_kernel(
    const float4* __restrict__ x4,
    const int* __restrict__ ptr,
    float* __restrict__ out,      // scalar for atomics
    int n_rows, int n_segs)
{
    __shared__ int sptr[MAX_PTR];
    for (int i = threadIdx.x; i <= n_segs; i += blockDim.x)
        sptr[i] = ptr[i];
    __syncthreads();

    const int base = blockIdx.x * CHUNK;
    const int chunk_end = min(base + CHUNK, n_rows);
    const int c4 = threadIdx.x & 31;   // float4 column
    const int r  = threadIdx.x >> 5;   // row lane 0..7

    int row = base + r;
    if (row >= chunk_end) return;

    // Binary search: largest seg with sptr[seg] <= row.
    int lo = 0, hi = n_segs - 1;
    while (lo < hi) {
        int mid = (lo + hi + 1) >> 1;
        if (sptr[mid] <= row) lo = mid; else hi = mid - 1;
    }
    int seg = lo;
    int seg_end = sptr[seg + 1];

    float4 acc = make_float4(0.f, 0.f, 0.f, 0.f);
    const int out_col = c4 * 4;

    #pragma unroll 4
    for (; row < chunk_end; row += 8) {
        if (row >= seg_end) {
            float* o = out + (size_t)seg * D_FEAT + out_col;
            atomicAdd(o + 0, acc.x);
            atomicAdd(o + 1, acc.y);
            atomicAdd(o + 2, acc.z);
            atomicAdd(o + 3, acc.w);
            acc = make_float4(0.f, 0.f, 0.f, 0.f);
            do { seg++; seg_end = sptr[seg + 1]; } while (row >= seg_end);
        }
        const float4 v = x4[(size_t)row * D4 + c4];
        acc.x += v.x; acc.y += v.y; acc.z += v.z; acc.w += v.w;
    }

    float* o = out + (size_t)seg * D_FEAT + out_col;
    atomicAdd(o + 0, acc.x);
    atomicAdd(o + 1, acc.y);
    atomicAdd(o + 2, acc.z);
    atomicAdd(o + 3, acc.w);
}

__global__ __launch_bounds__(256) void finalize_kernel(
    float4* __restrict__ out4,
    const int* __restrict__ ptr,
    int n_segs)
{
    int i = blockIdx.x * blockDim.x + threadIdx.x;   // float4 index
    if (i >= n_segs * D4) return;
    int seg = i >> 5;                                 // /D4
    int cnt = ptr[seg + 1] - ptr[seg];
    float inv = 1.0f / (float)(cnt > 0 ? cnt : 1);
    float4 v = out4[i];
    v.x *= inv; v.y *= inv; v.z *= inv; v.w *= inv;
    out4[i] = v;
}

extern "C" void kernel_launch(void* const* d_in, const int* in_sizes, int n_in,
                              void* d_out, int out_size)
{
    const float4* x4  = (const float4*)d_in[0];
    const int*    ptr = (const int*)d_in[1];
    float*        out = (float*)d_out;

    const int n_rows  = in_sizes[0] / D_FEAT;        // 524288
    const int n_segs  = in_sizes[1] - 1;             // 1024
    const int out_f4  = out_size / 4;                // 32768

    zero_out_kernel<<<(out_f4 + 255) / 256, 256>>>((float4*)out, out_f4);

    const int n_chunks = (n_rows + CHUNK - 1) / CHUNK;   // 2048
    seg_accum_kernel<<<n_chunks, 256>>>(x4, ptr, out, n_rows, n_segs);

    finalize_kernel<<<(out_f4 + 255) / 256, 256>>>((float4*)out, ptr, n_segs);
}

// round 3
// speedup vs baseline: 1.3567x; 1.1081x over previous
#include <cuda_runtime.h>

// Segment mean pooling, split-K with zero-maintained device scratch:
//   x: [N=524288, D=128] f32, pointer: [B+1=1025] i32, out: [B=1024, D=128] f32.
//
// Kernel 1 (accum): uniform 256-row chunks per CTA. The set of segments
//   overlapping a chunk is CTA-uniform, so we loop segment-by-segment and run
//   a branch-free unrolled row loop per intersection (loads front-batch ->
//   high MLP). Partials flushed via atomicAdd into g_scratch (starts zero).
// Kernel 2 (finalize): out = scratch * 1/max(cnt,1); scratch reset to zero,
//   restoring the invariant for the next graph replay.

#define D_FEAT 128
#define D4 (D_FEAT / 4)     // 32 float4 per row
#define CHUNK 256           // rows per CTA
#define NSEG 1024

__device__ float g_scratch[NSEG * D_FEAT];   // zero-initialized, kept zero

__global__ __launch_bounds__(256) void seg_accum_kernel(
    const float4* __restrict__ x4,
    const int* __restrict__ ptr,
    int n_rows, int n_segs)
{
    const int base = blockIdx.x * CHUNK;
    if (base >= n_rows) return;
    const int cend = min(base + CHUNK, n_rows);
    const int c4 = threadIdx.x & 31;   // float4 column 0..31
    const int r  = threadIdx.x >> 5;   // row lane 0..7

    // First segment overlapping this chunk: largest seg with ptr[seg] <= base.
    // Key is CTA-uniform -> all threads hit the same ptr addresses (broadcast).
    int lo = 0, hi = n_segs - 1;
    while (lo < hi) {
        int mid = (lo + hi + 1) >> 1;
        if (__ldg(ptr + mid) <= base) lo = mid; else hi = mid - 1;
    }
    int seg = lo;

    for (;;) {
        const int seg_end = __ldg(ptr + seg + 1);
        const int s = max(__ldg(ptr + seg), base);
        const int e = min(seg_end, cend);

        if (e > s) {
            float4 acc = make_float4(0.f, 0.f, 0.f, 0.f);
            #pragma unroll 4
            for (int row = s + r; row < e; row += 8) {
                const float4 v = x4[(size_t)row * D4 + c4];
                acc.x += v.x; acc.y += v.y; acc.z += v.z; acc.w += v.w;
            }
            if (s + r < e) {   // this lane touched >=1 row
                float* o = g_scratch + (size_t)seg * D_FEAT + c4 * 4;
                atomicAdd(o + 0, acc.x);
                atomicAdd(o + 1, acc.y);
                atomicAdd(o + 2, acc.z);
                atomicAdd(o + 3, acc.w);
            }
        }
        if (seg_end >= cend) break;
        seg++;
    }
}

__global__ __launch_bounds__(256) void finalize_kernel(
    float4* __restrict__ out4,
    const int* __restrict__ ptr,
    int n_segs)
{
    const int i = blockIdx.x * blockDim.x + threadIdx.x;   // float4 index
    if (i >= n_segs * D4) return;
    const int seg = i >> 5;                                 // / D4
    const int cnt = __ldg(ptr + seg + 1) - __ldg(ptr + seg);
    const float inv = 1.0f / (float)(cnt > 0 ? cnt : 1);

    float4* s4 = (float4*)g_scratch;
    float4 v = s4[i];
    v.x *= inv; v.y *= inv; v.z *= inv; v.w *= inv;
    out4[i] = v;
    s4[i] = make_float4(0.f, 0.f, 0.f, 0.f);   // restore zero invariant
}

extern "C" void kernel_launch(void* const* d_in, const int* in_sizes, int n_in,
                              void* d_out, int out_size)
{
    const float4* x4  = (const float4*)d_in[0];
    const int*    ptr = (const int*)d_in[1];
    float4*       o4  = (float4*)d_out;

    const int n_rows = in_sizes[0] / D_FEAT;   // 524288
    const int n_segs = in_sizes[1] - 1;        // 1024

    const int n_chunks = (n_rows + CHUNK - 1) / CHUNK;   // 2048
    seg_accum_kernel<<<n_chunks, 256>>>(x4, ptr, n_rows, n_segs);

    const int out_f4 = out_size / 4;           // 32768
    finalize_kernel<<<(out_f4 + 255) / 256, 256>>>(o4, ptr, n_segs);
}

// round 4
// speedup vs baseline: 1.5693x; 1.1567x over previous
#include <cuda_runtime.h>

// Segment mean pooling: x [524288,128] f32, pointer [1025] i32 -> out [1024,128] f32.
//
// Kernel 1: zero out (out is poisoned by the harness).
// Kernel 2: uniform 512-row chunks per CTA (grid=1024 -> single wave at occ 8).
//   For each CTA-uniform segment-intersection, 8 row-lane warps accumulate
//   float4 partials, reduce them across warps in smem, scale by 1/cnt, and
//   warp 0 alone flushes with scalar atomicAdd into out (8x fewer RED lanes).
//   Sum of inv-scaled partials == mean, so no finalize pass is needed.

#define D_FEAT 128
#define D4 (D_FEAT / 4)     // 32 float4 per row
#define CHUNK 512           // rows per CTA

__global__ __launch_bounds__(256) void zero_out_kernel(float4* __restrict__ out4, int n4)
{
    int i = blockIdx.x * blockDim.x + threadIdx.x;
    if (i < n4) out4[i] = make_float4(0.f, 0.f, 0.f, 0.f);
}

__global__ __launch_bounds__(256) void seg_accum_kernel(
    const float4* __restrict__ x4,
    const int* __restrict__ ptr,
    float* __restrict__ out,
    int n_rows, int n_segs)
{
    const int base = blockIdx.x * CHUNK;
    if (base >= n_rows) return;
    const int cend = min(base + CHUNK, n_rows);
    const int c4 = threadIdx.x & 31;   // float4 column 0..31
    const int r  = threadIdx.x >> 5;   // row lane (warp id) 0..7

    __shared__ float4 sred[8][D4];     // 4 KB

    // First segment overlapping the chunk (CTA-uniform binary search; all
    // threads hit the same ptr addresses -> broadcast L1 hits).
    int lo = 0, hi = n_segs - 1;
    while (lo < hi) {
        int mid = (lo + hi + 1) >> 1;
        if (__ldg(ptr + mid) <= base) lo = mid; else hi = mid - 1;
    }
    int seg = lo;

    for (;;) {
        const int seg_beg = __ldg(ptr + seg);
        const int seg_end = __ldg(ptr + seg + 1);
        const int s = max(seg_beg, base);
        const int e = min(seg_end, cend);

        float4 acc = make_float4(0.f, 0.f, 0.f, 0.f);
        #pragma unroll 4
        for (int row = s + r; row < e; row += 8) {
            const float4 v = x4[(size_t)row * D4 + c4];
            acc.x += v.x; acc.y += v.y; acc.z += v.z; acc.w += v.w;
        }

        // Cross-warp reduction: 8 partials per column -> 1, then warp 0 flushes.
        sred[r][c4] = acc;
        __syncthreads();
        if (r == 0) {
            #pragma unroll
            for (int i = 1; i < 8; i++) {
                const float4 v = sred[i][c4];
                acc.x += v.x; acc.y += v.y; acc.z += v.z; acc.w += v.w;
            }
            const int cnt = seg_end - seg_beg;
            const float inv = 1.0f / (float)(cnt > 0 ? cnt : 1);
            float* o = out + (size_t)seg * D_FEAT + c4 * 4;
            atomicAdd(o + 0, acc.x * inv);
            atomicAdd(o + 1, acc.y * inv);
            atomicAdd(o + 2, acc.z * inv);
            atomicAdd(o + 3, acc.w * inv);
        }
        if (seg_end >= cend) break;
        seg++;
        __syncthreads();   // smem buffer reuse safety
    }
}

extern "C" void kernel_launch(void* const* d_in, const int* in_sizes, int n_in,
                              void* d_out, int out_size)
{
    const float4* x4  = (const float4*)d_in[0];
    const int*    ptr = (const int*)d_in[1];
    float*        out = (float*)d_out;

    const int n_rows = in_sizes[0] / D_FEAT;   // 524288
    const int n_segs = in_sizes[1] - 1;        // 1024
    const int out_f4 = out_size / 4;           // 32768

    zero_out_kernel<<<(out_f4 + 255) / 256, 256>>>((float4*)out, out_f4);

    const int n_chunks = (n_rows + CHUNK - 1) / CHUNK;   // 1024
    seg_accum_kernel<<<n_chunks, 256>>>(x4, ptr, out, n_rows, n_segs);
}